// round 17
// baseline (speedup 1.0000x reference)
#include <cuda_runtime.h>
#include <cuda_bf16.h>
#include <cstdint>

// BoundaryLoss fused kernel, v16: two-batch interleave (2 independent
// memory streams per thread).
//  - 256 threads/block, 2 cols/thread; tile = 512 cols x 16 rows, processed
//    simultaneously for batches b and b+16 -> per iteration each thread
//    issues 8 loads across two independent dependence chains (2x MLP)
//  - horizontal 5-sum via overlapping float2 loads (no shuffles)
//  - vertical 5-sum: running window (+new -old, exact small-int fp)
//  - center target re-loaded from L1 (same addr as 2 iters ago)
//  - 512 blocks x 256 thr, ~3.5 blocks/SM: one clean wave
//  - last-block finalize (threadfence + ticket), double accumulation

#define BATCH 32
#define HT 512
#define WD 512
#define ROWS 16                       // output rows per block
#define ITERS (ROWS + 4)              // 20 streamed rows
#define GRID_Y (HT / ROWS)            // 32
#define GRID_B (BATCH / 2)            // 16 batch-pairs
#define NBLK (GRID_Y * GRID_B)        // 512
#define NTHR 256

__device__ double g_partials[NBLK];
__device__ unsigned int g_count;      // zero-init; reset by last block each launch

__device__ __forceinline__ void bce_w(float x, float t, float s, float& acc) {
    // weight: 5 inside boundary band (0 < boxsum < 25), else 1 (boxsum exact int)
    const float w = (s > 0.5f && s < 24.5f) ? 5.0f : 1.0f;
    // BCE(sigmoid(x), t) = softplus(x) - t*x; stable fast-math softplus
    const float sp = __logf(1.0f + __expf(-fabsf(x))) + fmaxf(x, 0.0f);
    acc = fmaf(fmaf(-x, t, sp), w, acc);
}

__global__ __launch_bounds__(NTHR, 4)
void boundary_loss_kernel(const float* __restrict__ pred,
                          const float* __restrict__ target,
                          float* __restrict__ out) {
    const int tid  = threadIdx.x;        // 0..255
    const int lane = tid & 31;
    const int wid  = tid >> 5;           // 0..7
    const int c0   = tid * 2;            // this thread's 2 columns

    const int by = blockIdx.x;           // row-chunk  (0..31)
    const int bp = blockIdx.y;           // batch pair (0..15)
    const int b0 = bp;                   // first batch
    const int b1 = bp + GRID_B;          // second batch
    const int r_base = by * ROWS - 2;    // first streamed row (may be -2)

    const float* tbase0 = target + (size_t)b0 * HT * WD + (ptrdiff_t)r_base * WD + c0;
    const float* tbase1 = target + (size_t)b1 * HT * WD + (ptrdiff_t)r_base * WD + c0;
    const float* pbase0 = pred + (size_t)b0 * HT * WD + (size_t)(by * ROWS) * WD + c0;
    const float* pbase1 = pred + (size_t)b1 * HT * WD + (size_t)(by * ROWS) * WD + c0;

    const bool has_left  = (c0 > 0);          // false only at image col 0
    const bool has_right = (c0 + 2 < WD);     // false only at image col 510

    float2 hrA[5], hrB[5];               // horizontal 5-sum rings per stream
    float2 vsA = make_float2(0.f, 0.f);
    float2 vsB = make_float2(0.f, 0.f);
    float accA = 0.0f, accB = 0.0f;

    #pragma unroll
    for (int j = 0; j < ITERS; j++) {
        const bool rv = (unsigned)(r_base + j) < (unsigned)HT;

        // 6 independent target loads (3 per stream), overlapping halos
        float2 tA  = make_float2(0.f, 0.f), tB  = make_float2(0.f, 0.f);
        float2 lA  = make_float2(0.f, 0.f), lB  = make_float2(0.f, 0.f);
        float2 rA  = make_float2(0.f, 0.f), rB  = make_float2(0.f, 0.f);
        if (rv) {
            tA = *(const float2*)(tbase0 + j * WD);
            tB = *(const float2*)(tbase1 + j * WD);
            if (has_left) {
                lA = *(const float2*)(tbase0 + j * WD - 2);
                lB = *(const float2*)(tbase1 + j * WD - 2);
            }
            if (has_right) {
                rA = *(const float2*)(tbase0 + j * WD + 2);
                rB = *(const float2*)(tbase1 + j * WD + 2);
            }
        }

        // horizontal 5-sums (5 FADD per stream, exact small-int)
        const float mA = lA.y + tA.x + tA.y + rA.x;
        const float mB = lB.y + tB.x + tB.y + rB.x;
        float2 hA, hB;
        hA.x = lA.x + mA;  hA.y = mA + rA.y;
        hB.x = lB.x + mB;  hB.y = mB + rB.y;

        // vertical running 5-window
        if (j >= 5) {
            const float2 oA = hrA[j % 5], oB = hrB[j % 5];
            vsA.x -= oA.x; vsA.y -= oA.y;
            vsB.x -= oB.x; vsB.y -= oB.y;
        }
        vsA.x += hA.x; vsA.y += hA.y;
        vsB.x += hB.x; vsB.y += hB.y;
        hrA[j % 5] = hA; hrB[j % 5] = hB;

        if (j >= 4) {
            // center targets: same addresses as iter j-2 loads -> L1 hits
            const float2 cA = *(const float2*)(tbase0 + (j - 2) * WD);
            const float2 cB = *(const float2*)(tbase1 + (j - 2) * WD);
            const float2 pA = __ldcs((const float2*)(pbase0 + (j - 4) * WD));
            const float2 pB = __ldcs((const float2*)(pbase1 + (j - 4) * WD));

            bce_w(pA.x, cA.x, vsA.x, accA);
            bce_w(pA.y, cA.y, vsA.y, accA);
            bce_w(pB.x, cB.x, vsB.x, accB);
            bce_w(pB.y, cB.y, vsB.y, accB);
        }
    }

    float acc = accA + accB;

    // ---- block reduction: warp fp32 -> smem -> double ----
    #pragma unroll
    for (int off = 16; off > 0; off >>= 1)
        acc += __shfl_xor_sync(0xFFFFFFFFu, acc, off);

    __shared__ float s_warp[8];
    __shared__ unsigned int s_islast;
    if (lane == 0) s_warp[wid] = acc;
    __syncthreads();

    if (tid == 0) {
        double d = 0.0;
        #pragma unroll
        for (int i = 0; i < 8; i++) d += (double)s_warp[i];
        const int bid = blockIdx.x + GRID_Y * blockIdx.y;
        g_partials[bid] = d;
        __threadfence();
        const unsigned int ticket = atomicAdd(&g_count, 1u);
        s_islast = (ticket == NBLK - 1) ? 1u : 0u;
    }
    __syncthreads();

    // ---- last block finalizes ----
    if (s_islast) {
        const volatile double* vp = (const volatile double*)g_partials;
        double d = vp[tid] + vp[tid + NTHR];

        #pragma unroll
        for (int off = 16; off > 0; off >>= 1)
            d += __shfl_xor_sync(0xFFFFFFFFu, d, off);

        __shared__ double s_dw[8];
        if (lane == 0) s_dw[wid] = d;
        __syncthreads();

        if (tid == 0) {
            double tot = 0.0;
            #pragma unroll
            for (int i = 0; i < 8; i++) tot += s_dw[i];
            out[0] = (float)(tot / ((double)BATCH * HT * WD));
            g_count = 0;     // reset for next graph replay
        }
    }
}

extern "C" void kernel_launch(void* const* d_in, const int* in_sizes, int n_in,
                              void* d_out, int out_size) {
    const float* pred   = (const float*)d_in[0];
    const float* target = (const float*)d_in[1];
    float* out = (float*)d_out;

    dim3 grid(GRID_Y, GRID_B);   // 32 x 16 = 512 blocks, single clean wave
    boundary_loss_kernel<<<grid, NTHR>>>(pred, target, out);
}